// round 8
// baseline (speedup 1.0000x reference)
#include <cuda_runtime.h>
#include <cuda_fp16.h>
#include <cstdint>

#define Bb 4
#define Qq 512
#define Kk 1024
#define VDd 256
#define Hh 128

#define AT2 68          // av attn smem stride
#define NSLAB 4
#define SLABK 256

// Scratch (no allocations allowed).
__device__ __align__(16) float g_qp[Bb * Qq * Hh];             // 1 MB
__device__ __align__(16) float g_kp[Bb * Kk * Hh];             // 2 MB
__device__ __align__(16) float g_sc[Bb * Qq * Kk];             // 8 MB
__device__ __align__(16) float g_pt[NSLAB][Bb * Qq * VDd];     // 8 MB partials

__device__ __forceinline__ unsigned int tanh2(unsigned int x) {
    unsigned int y;
    asm("tanh.approx.f16x2 %0, %1;" : "=r"(y) : "r"(x));
    return y;
}

// ---------------------------------------------------------------------------
// Combined projection: g_qp = queries@W_q, g_kp = keys@W_k. 384 blocks.
// ---------------------------------------------------------------------------
__global__ void __launch_bounds__(256)
proj_kernel(const float* __restrict__ queries,
            const float* __restrict__ W_q,
            const float* __restrict__ keys,
            const float* __restrict__ W_k) {
    __shared__ __align__(16) float a_s[16][260];
    __shared__ __align__(16) float w_t[128][36];

    const int bx = blockIdx.x;
    const float* A; const float* W; float* C; int row0;
    if (bx < (Bb * Qq) / 16) { A = queries; W = W_q; C = g_qp; row0 = bx * 16; }
    else { A = keys; W = W_k; C = g_kp; row0 = (bx - (Bb * Qq) / 16) * 16; }

    const int tid = threadIdx.x;

    const float4* A4 = (const float4*)(A + (size_t)row0 * 256);
    #pragma unroll
    for (int i = 0; i < 4; i++) {
        int e = i * 256 + tid;
        ((float4*)&a_s[e >> 6][0])[e & 63] = A4[e];
    }

    const int col = tid & 127;
    const int rg  = tid >> 7;
    float acc[8];
    #pragma unroll
    for (int i = 0; i < 8; i++) acc[i] = 0.f;

    for (int dc = 0; dc < 256; dc += 32) {
        __syncthreads();
        #pragma unroll
        for (int i = 0; i < 16; i++) {
            int idx = i * 256 + tid;
            int r = idx >> 7, c = idx & 127;
            w_t[c][r] = W[(size_t)(dc + r) * 128 + c];
        }
        __syncthreads();
        const float4* wv4 = (const float4*)&w_t[col][0];
        #pragma unroll
        for (int d4 = 0; d4 < 8; d4++) {
            float4 wv = wv4[d4];
            #pragma unroll
            for (int i = 0; i < 8; i++) {
                float4 av = ((const float4*)&a_s[rg * 8 + i][dc])[d4];
                acc[i] += av.x * wv.x + av.y * wv.y + av.z * wv.z + av.w * wv.w;
            }
        }
    }
    __syncthreads();
    #pragma unroll
    for (int i = 0; i < 8; i++)
        C[(size_t)(row0 + rg * 8 + i) * 128 + col] = acc[i];
}

// ---------------------------------------------------------------------------
// Scores: 64q x 64k tile, 4x4 micro-tile. q/k smem tiles are half2-packed
// (h, h+64) pairs, TRANSPOSED [h][row] -> inner LDS are uniform-row (no
// conflicts) and the hot loop has no pack conversions:
//   HADD2 -> tanh.approx.f16x2 -> 2 cvt -> 2 FFMA (f32 accumulate).
// Masked tiles (k0 >= valid_len) exit immediately.
// ---------------------------------------------------------------------------
__global__ void __launch_bounds__(256)
scores_kernel(const float* __restrict__ w_v,
              const int* __restrict__ valid_lens) {
    const int b  = blockIdx.z;
    const int k0 = blockIdx.x * 64;
    if (k0 >= valid_lens[b]) return;
    const int q0 = blockIdx.y * 64;

    __shared__ __align__(16) unsigned int qs2[64 * 64];   // [h][qrow] 16 KB
    __shared__ __align__(16) unsigned int ks2[64 * 64];   // [h][krow] 16 KB
    __shared__ float2 ws2[64];

    const int tid = threadIdx.x;
    const float4* qp4 = (const float4*)(g_qp + (size_t)(b * Qq + q0) * Hh);
    const float4* kp4 = (const float4*)(g_kp + (size_t)(b * Kk + k0) * Hh);

    // Load + pack + transpose. Task t: row = t&63, c4 = t>>6 (f4 col 0..15).
    #pragma unroll
    for (int i = 0; i < 4; i++) {
        int t   = i * 256 + tid;
        int row = t & 63, c4 = t >> 6;
        float4 qa = qp4[row * 32 + c4];
        float4 qb = qp4[row * 32 + c4 + 16];   // h+64 half
        float4 ka = kp4[row * 32 + c4];
        float4 kb = kp4[row * 32 + c4 + 16];
        __half2 q0h = __floats2half2_rn(qa.x, qb.x);
        __half2 q1h = __floats2half2_rn(qa.y, qb.y);
        __half2 q2h = __floats2half2_rn(qa.z, qb.z);
        __half2 q3h = __floats2half2_rn(qa.w, qb.w);
        __half2 k0h = __floats2half2_rn(ka.x, kb.x);
        __half2 k1h = __floats2half2_rn(ka.y, kb.y);
        __half2 k2h = __floats2half2_rn(ka.z, kb.z);
        __half2 k3h = __floats2half2_rn(ka.w, kb.w);
        int c = 4 * c4;
        qs2[(c + 0) * 64 + row] = *(unsigned int*)&q0h;
        qs2[(c + 1) * 64 + row] = *(unsigned int*)&q1h;
        qs2[(c + 2) * 64 + row] = *(unsigned int*)&q2h;
        qs2[(c + 3) * 64 + row] = *(unsigned int*)&q3h;
        ks2[(c + 0) * 64 + row] = *(unsigned int*)&k0h;
        ks2[(c + 1) * 64 + row] = *(unsigned int*)&k1h;
        ks2[(c + 2) * 64 + row] = *(unsigned int*)&k2h;
        ks2[(c + 3) * 64 + row] = *(unsigned int*)&k3h;
    }
    if (tid < 64) ws2[tid] = make_float2(w_v[tid], w_v[tid + 64]);
    __syncthreads();

    const int tx = tid & 15;   // k group (rows 4tx..4tx+3 of k tile)
    const int ty = tid >> 4;   // q group (rows 4ty..4ty+3 of q tile)

    float acc[4][4];
    #pragma unroll
    for (int i = 0; i < 4; i++)
        #pragma unroll
        for (int j = 0; j < 4; j++) acc[i][j] = 0.f;

    #pragma unroll 2
    for (int h = 0; h < 64; h++) {
        float2 wv = ws2[h];
        uint4 qq = *(const uint4*)&qs2[h * 64 + 4 * ty];
        uint4 kk = *(const uint4*)&ks2[h * 64 + 4 * tx];
        unsigned int qa[4] = {qq.x, qq.y, qq.z, qq.w};
        unsigned int ka[4] = {kk.x, kk.y, kk.z, kk.w};
        #pragma unroll
        for (int i = 0; i < 4; i++) {
            __half2 qh = *(__half2*)&qa[i];
            #pragma unroll
            for (int j = 0; j < 4; j++) {
                __half2 kh = *(__half2*)&ka[j];
                __half2 s  = __hadd2(qh, kh);
                unsigned int t = tanh2(*(unsigned int*)&s);
                __half2 th = *(__half2*)&t;
                acc[i][j] += wv.x * __low2float(th) + wv.y * __high2float(th);
            }
        }
    }

    #pragma unroll
    for (int i = 0; i < 4; i++) {
        float4 r = make_float4(acc[i][0], acc[i][1], acc[i][2], acc[i][3]);
        *(float4*)&g_sc[(size_t)(b * Qq + q0 + 4 * ty + i) * Kk + k0 + 4 * tx] = r;
    }
}

// ---------------------------------------------------------------------------
// Softmax over k < vl; zeros written up to roundup(vl,64) (AV reads that far).
// ---------------------------------------------------------------------------
__global__ void softmax_kernel(const int* __restrict__ valid_lens) {
    const int row = blockIdx.x;
    const int b   = row >> 9;
    const int vl  = valid_lens[b];
    const int vl64 = (vl + 63) & ~63;
    const int tid = threadIdx.x;
    const float NINF = __int_as_float(0xff800000);

    float4* p = (float4*)&g_sc[(size_t)row * Kk];
    const int k = 4 * tid;
    const bool live = (k < vl64);
    float4 v = live ? p[tid] : make_float4(NINF, NINF, NINF, NINF);
    float e0 = (k     < vl) ? v.x : NINF;
    float e1 = (k + 1 < vl) ? v.y : NINF;
    float e2 = (k + 2 < vl) ? v.z : NINF;
    float e3 = (k + 3 < vl) ? v.w : NINF;

    __shared__ float redm[8];
    __shared__ float reds[8];
    const int wid = tid >> 5, lid = tid & 31;

    float m = fmaxf(fmaxf(e0, e1), fmaxf(e2, e3));
    #pragma unroll
    for (int o = 16; o; o >>= 1) m = fmaxf(m, __shfl_xor_sync(~0u, m, o));
    if (lid == 0) redm[wid] = m;
    __syncthreads();
    m = redm[0];
    #pragma unroll
    for (int i = 1; i < 8; i++) m = fmaxf(m, redm[i]);

    float p0 = (k     < vl) ? __expf(e0 - m) : 0.f;
    float p1 = (k + 1 < vl) ? __expf(e1 - m) : 0.f;
    float p2 = (k + 2 < vl) ? __expf(e2 - m) : 0.f;
    float p3 = (k + 3 < vl) ? __expf(e3 - m) : 0.f;

    float s = p0 + p1 + p2 + p3;
    #pragma unroll
    for (int o = 16; o; o >>= 1) s += __shfl_xor_sync(~0u, s, o);
    if (lid == 0) reds[wid] = s;
    __syncthreads();
    s = reds[0];
    #pragma unroll
    for (int i = 1; i < 8; i++) s += reds[i];

    float inv = __frcp_rn(s);
    if (live) p[tid] = make_float4(p0 * inv, p1 * inv, p2 * inv, p3 * inv);
}

// ---------------------------------------------------------------------------
// AV partial: k split in NSLAB=4 256-wide slabs -> g_pt[s]. Tile 32q x 64v,
// 256 thr, 2q x 4v per thread, k-chunk 64, register double-buffered.
// Grid (VD/64, Q/32, NSLAB*B): b = z>>2, s = z&3. 1024 blocks.
// ---------------------------------------------------------------------------
__global__ void __launch_bounds__(256)
av_kernel(const float* __restrict__ values,
          const int* __restrict__ valid_lens) {
    __shared__ __align__(16) float at_s[32 * AT2];
    __shared__ __align__(16) float vs_s[64 * 64];

    const int z   = blockIdx.z;
    const int b   = z >> 2;
    const int s   = z & 3;
    const int vl  = valid_lens[b];
    const int kbeg = s * SLABK;
    if (kbeg >= vl) return;                  // slab never read by reduce
    const int kend = (vl < kbeg + SLABK) ? vl : (kbeg + SLABK);

    const int q0  = blockIdx.y * 32;
    const int v0  = blockIdx.x * 64;
    const int tid = threadIdx.x;
    const int tx  = tid & 15;
    const int ty  = tid >> 4;

    const float* attn = g_sc + (size_t)(b * Qq + q0) * Kk + kbeg;
    const float* vals = values + ((size_t)b * Kk + kbeg) * VDd + v0;

    const int ar0 = tid >> 4,          ac0 = tid & 15;
    const int ar1 = (tid + 256) >> 4;
    const int vr0 = ar0, vr1 = ar1;
    const int vr2 = (tid + 512) >> 4, vr3 = (tid + 768) >> 4;

    float4 pa0, pa1, pv0, pv1, pv2, pv3;
    pa0 = ((const float4*)(attn + (size_t)ar0 * Kk))[ac0];
    pa1 = ((const float4*)(attn + (size_t)ar1 * Kk))[ac0];
    pv0 = ((const float4*)(vals + (size_t)vr0 * VDd))[ac0];
    pv1 = ((const float4*)(vals + (size_t)vr1 * VDd))[ac0];
    pv2 = ((const float4*)(vals + (size_t)vr2 * VDd))[ac0];
    pv3 = ((const float4*)(vals + (size_t)vr3 * VDd))[ac0];

    float4 acc0 = make_float4(0.f, 0.f, 0.f, 0.f);
    float4 acc1 = acc0;

    const int nchunk = (kend - kbeg + 63) >> 6;
    for (int c = 0; c < nchunk; c++) {
        ((float4*)(at_s + ar0 * AT2))[ac0] = pa0;
        ((float4*)(at_s + ar1 * AT2))[ac0] = pa1;
        ((float4*)vs_s)[vr0 * 16 + ac0] = pv0;
        ((float4*)vs_s)[vr1 * 16 + ac0] = pv1;
        ((float4*)vs_s)[vr2 * 16 + ac0] = pv2;
        ((float4*)vs_s)[vr3 * 16 + ac0] = pv3;
        __syncthreads();

        if (c + 1 < nchunk) {
            const float* an = attn + (c + 1) * 64;
            const float* vn = vals + (size_t)(c + 1) * 64 * VDd;
            pa0 = ((const float4*)(an + (size_t)ar0 * Kk))[ac0];
            pa1 = ((const float4*)(an + (size_t)ar1 * Kk))[ac0];
            pv0 = ((const float4*)(vn + (size_t)vr0 * VDd))[ac0];
            pv1 = ((const float4*)(vn + (size_t)vr1 * VDd))[ac0];
            pv2 = ((const float4*)(vn + (size_t)vr2 * VDd))[ac0];
            pv3 = ((const float4*)(vn + (size_t)vr3 * VDd))[ac0];
        }

        const float* a0 = at_s + (2 * ty) * AT2;
        const float* a1 = a0 + AT2;
        const float4* vrow = (const float4*)vs_s + tx;
        #pragma unroll 16
        for (int k = 0; k < 64; k++) {
            float w0 = a0[k], w1 = a1[k];
            float4 vv = vrow[k * 16];
            acc0.x += w0 * vv.x; acc0.y += w0 * vv.y;
            acc0.z += w0 * vv.z; acc0.w += w0 * vv.w;
            acc1.x += w1 * vv.x; acc1.y += w1 * vv.y;
            acc1.z += w1 * vv.z; acc1.w += w1 * vv.w;
        }
        __syncthreads();
    }

    float* pt = g_pt[s];
    float4* o0 = (float4*)(pt + (size_t)(b * Qq + q0 + 2 * ty) * VDd + v0);
    float4* o1 = (float4*)(pt + (size_t)(b * Qq + q0 + 2 * ty + 1) * VDd + v0);
    o0[tx] = acc0;
    o1[tx] = acc1;
}

// ---------------------------------------------------------------------------
// Reduce: out = sum over live slabs (s*SLABK < vl). 512 blocks x 256 thr.
// ---------------------------------------------------------------------------
__global__ void reduce_kernel(const int* __restrict__ valid_lens,
                              float* __restrict__ out) {
    const int e4 = blockIdx.x * 256 + threadIdx.x;    // float4 index
    const int b  = e4 >> 15;                          // (e4*4)/(Qq*VDd)
    const int vl = valid_lens[b];
    float4 r = ((const float4*)g_pt[0])[e4];
    #pragma unroll
    for (int s = 1; s < NSLAB; s++) {
        if (s * SLABK < vl) {
            float4 r1 = ((const float4*)g_pt[s])[e4];
            r.x += r1.x; r.y += r1.y; r.z += r1.z; r.w += r1.w;
        }
    }
    ((float4*)out)[e4] = r;
}

// ---------------------------------------------------------------------------
extern "C" void kernel_launch(void* const* d_in, const int* in_sizes, int n_in,
                              void* d_out, int out_size) {
    const float* queries    = (const float*)d_in[0];
    const float* keys       = (const float*)d_in[1];
    const float* values     = (const float*)d_in[2];
    const int*   valid_lens = (const int*)  d_in[3];
    const float* W_q        = (const float*)d_in[4];
    const float* W_k        = (const float*)d_in[5];
    const float* w_v        = (const float*)d_in[6];
    float* out = (float*)d_out;

    proj_kernel<<<(Bb * Qq) / 16 + (Bb * Kk) / 16, 256>>>(queries, W_q, keys, W_k);

    scores_kernel<<<dim3(Kk / 64, Qq / 64, Bb), 256>>>(w_v, valid_lens);

    softmax_kernel<<<Bb * Qq, 256>>>(valid_lens);

    av_kernel<<<dim3(VDd / 64, Qq / 32, NSLAB * Bb), 256>>>(values, valid_lens);

    reduce_kernel<<<(Bb * Qq * VDd) / 1024, 256>>>(valid_lens, out);
}

// round 9
// speedup vs baseline: 1.1626x; 1.1626x over previous
#include <cuda_runtime.h>
#include <cuda_fp16.h>
#include <cstdint>

#define Bb 4
#define Qq 512
#define Kk 1024
#define VDd 256
#define Hh 128

#define AT2 68          // av attn smem stride
#define NSLAB 4
#define SLABK 256

// Scratch (no allocations allowed).
__device__ __align__(16) float g_qp[Bb * Qq * Hh];             // 1 MB
__device__ __align__(16) float g_kp[Bb * Kk * Hh];             // 2 MB
__device__ __align__(16) float g_sc[Bb * Qq * Kk];             // 8 MB
__device__ __align__(16) float g_pt[NSLAB][Bb * Qq * VDd];     // 8 MB partials

__device__ __forceinline__ unsigned int tanh2(unsigned int x) {
    unsigned int y;
    asm("tanh.approx.f16x2 %0, %1;" : "=r"(y) : "r"(x));
    return y;
}

// ---------------------------------------------------------------------------
// Combined projection: g_qp = queries@W_q, g_kp = keys@W_k. 384 blocks.
// ---------------------------------------------------------------------------
__global__ void __launch_bounds__(256)
proj_kernel(const float* __restrict__ queries,
            const float* __restrict__ W_q,
            const float* __restrict__ keys,
            const float* __restrict__ W_k) {
    __shared__ __align__(16) float a_s[16][260];
    __shared__ __align__(16) float w_t[128][36];

    const int bx = blockIdx.x;
    const float* A; const float* W; float* C; int row0;
    if (bx < (Bb * Qq) / 16) { A = queries; W = W_q; C = g_qp; row0 = bx * 16; }
    else { A = keys; W = W_k; C = g_kp; row0 = (bx - (Bb * Qq) / 16) * 16; }

    const int tid = threadIdx.x;

    const float4* A4 = (const float4*)(A + (size_t)row0 * 256);
    #pragma unroll
    for (int i = 0; i < 4; i++) {
        int e = i * 256 + tid;
        ((float4*)&a_s[e >> 6][0])[e & 63] = A4[e];
    }

    const int col = tid & 127;
    const int rg  = tid >> 7;
    float acc[8];
    #pragma unroll
    for (int i = 0; i < 8; i++) acc[i] = 0.f;

    for (int dc = 0; dc < 256; dc += 32) {
        __syncthreads();
        #pragma unroll
        for (int i = 0; i < 16; i++) {
            int idx = i * 256 + tid;
            int r = idx >> 7, c = idx & 127;
            w_t[c][r] = W[(size_t)(dc + r) * 128 + c];
        }
        __syncthreads();
        const float4* wv4 = (const float4*)&w_t[col][0];
        #pragma unroll
        for (int d4 = 0; d4 < 8; d4++) {
            float4 wv = wv4[d4];
            #pragma unroll
            for (int i = 0; i < 8; i++) {
                float4 av = ((const float4*)&a_s[rg * 8 + i][dc])[d4];
                acc[i] += av.x * wv.x + av.y * wv.y + av.z * wv.z + av.w * wv.w;
            }
        }
    }
    __syncthreads();
    #pragma unroll
    for (int i = 0; i < 8; i++)
        C[(size_t)(row0 + rg * 8 + i) * 128 + col] = acc[i];
}

// ---------------------------------------------------------------------------
// Scores: 64q x 64k tile, 4x4 micro-tile. q/k tiles half2-packed (h, h+64),
// transposed [h][row]. Hot loop per h-pair: HADD2 + tanh2 + HFMA2 (no cvt!).
// fp16 partial accs flushed to fp32 every 16 h-pairs.
// Masked tiles (k0 >= valid_len) exit immediately.
// ---------------------------------------------------------------------------
__global__ void __launch_bounds__(256)
scores_kernel(const float* __restrict__ w_v,
              const int* __restrict__ valid_lens) {
    const int b  = blockIdx.z;
    const int k0 = blockIdx.x * 64;
    if (k0 >= valid_lens[b]) return;
    const int q0 = blockIdx.y * 64;

    __shared__ __align__(16) unsigned int qs2[64 * 64];   // [h][qrow] 16 KB
    __shared__ __align__(16) unsigned int ks2[64 * 64];   // [h][krow] 16 KB
    __shared__ unsigned int ws2h[64];                      // half2 (w_h, w_h+64)

    const int tid = threadIdx.x;
    const float4* qp4 = (const float4*)(g_qp + (size_t)(b * Qq + q0) * Hh);
    const float4* kp4 = (const float4*)(g_kp + (size_t)(b * Kk + k0) * Hh);

    // Load + pack + transpose. Task t: row = t&63, c4 = t>>6 (f4 col 0..15).
    #pragma unroll
    for (int i = 0; i < 4; i++) {
        int t   = i * 256 + tid;
        int row = t & 63, c4 = t >> 6;
        float4 qa = qp4[row * 32 + c4];
        float4 qb = qp4[row * 32 + c4 + 16];   // h+64 half
        float4 ka = kp4[row * 32 + c4];
        float4 kb = kp4[row * 32 + c4 + 16];
        __half2 h0, h1, h2, h3;
        h0 = __floats2half2_rn(qa.x, qb.x);
        h1 = __floats2half2_rn(qa.y, qb.y);
        h2 = __floats2half2_rn(qa.z, qb.z);
        h3 = __floats2half2_rn(qa.w, qb.w);
        int c = 4 * c4;
        qs2[(c + 0) * 64 + row] = *(unsigned int*)&h0;
        qs2[(c + 1) * 64 + row] = *(unsigned int*)&h1;
        qs2[(c + 2) * 64 + row] = *(unsigned int*)&h2;
        qs2[(c + 3) * 64 + row] = *(unsigned int*)&h3;
        h0 = __floats2half2_rn(ka.x, kb.x);
        h1 = __floats2half2_rn(ka.y, kb.y);
        h2 = __floats2half2_rn(ka.z, kb.z);
        h3 = __floats2half2_rn(ka.w, kb.w);
        ks2[(c + 0) * 64 + row] = *(unsigned int*)&h0;
        ks2[(c + 1) * 64 + row] = *(unsigned int*)&h1;
        ks2[(c + 2) * 64 + row] = *(unsigned int*)&h2;
        ks2[(c + 3) * 64 + row] = *(unsigned int*)&h3;
    }
    if (tid < 64) {
        __half2 w = __floats2half2_rn(w_v[tid], w_v[tid + 64]);
        ws2h[tid] = *(unsigned int*)&w;
    }
    __syncthreads();

    const int tx = tid & 15;   // k rows 4tx..4tx+3
    const int ty = tid >> 4;   // q rows 4ty..4ty+3

    float acc[4][4];
    #pragma unroll
    for (int i = 0; i < 4; i++)
        #pragma unroll
        for (int j = 0; j < 4; j++) acc[i][j] = 0.f;

    #pragma unroll
    for (int g = 0; g < 4; g++) {          // groups of 16 h-pairs
        __half2 hacc[4][4];
        #pragma unroll
        for (int i = 0; i < 4; i++)
            #pragma unroll
            for (int j = 0; j < 4; j++) hacc[i][j] = __floats2half2_rn(0.f, 0.f);

        #pragma unroll 4
        for (int h8 = 0; h8 < 16; h8++) {
            const int h = g * 16 + h8;
            unsigned int wv = ws2h[h];
            __half2 wh = *(__half2*)&wv;
            uint4 qq = *(const uint4*)&qs2[h * 64 + 4 * ty];
            uint4 kk = *(const uint4*)&ks2[h * 64 + 4 * tx];
            unsigned int qa[4] = {qq.x, qq.y, qq.z, qq.w};
            unsigned int ka[4] = {kk.x, kk.y, kk.z, kk.w};
            #pragma unroll
            for (int i = 0; i < 4; i++) {
                __half2 qh = *(__half2*)&qa[i];
                #pragma unroll
                for (int j = 0; j < 4; j++) {
                    __half2 kh = *(__half2*)&ka[j];
                    __half2 s  = __hadd2(qh, kh);
                    unsigned int t = tanh2(*(unsigned int*)&s);
                    hacc[i][j] = __hfma2(*(__half2*)&t, wh, hacc[i][j]);
                }
            }
        }
        // Flush fp16 partials to fp32.
        #pragma unroll
        for (int i = 0; i < 4; i++)
            #pragma unroll
            for (int j = 0; j < 4; j++) {
                float2 f = __half22float2(hacc[i][j]);
                acc[i][j] += f.x + f.y;
            }
    }

    #pragma unroll
    for (int i = 0; i < 4; i++) {
        float4 r = make_float4(acc[i][0], acc[i][1], acc[i][2], acc[i][3]);
        *(float4*)&g_sc[(size_t)(b * Qq + q0 + 4 * ty + i) * Kk + k0 + 4 * tx] = r;
    }
}

// ---------------------------------------------------------------------------
// Softmax over k < vl; zeros written up to roundup(vl,64) (AV reads that far).
// ---------------------------------------------------------------------------
__global__ void softmax_kernel(const int* __restrict__ valid_lens) {
    const int row = blockIdx.x;
    const int b   = row >> 9;
    const int vl  = valid_lens[b];
    const int vl64 = (vl + 63) & ~63;
    const int tid = threadIdx.x;
    const float NINF = __int_as_float(0xff800000);

    float4* p = (float4*)&g_sc[(size_t)row * Kk];
    const int k = 4 * tid;
    const bool live = (k < vl64);
    float4 v = live ? p[tid] : make_float4(NINF, NINF, NINF, NINF);
    float e0 = (k     < vl) ? v.x : NINF;
    float e1 = (k + 1 < vl) ? v.y : NINF;
    float e2 = (k + 2 < vl) ? v.z : NINF;
    float e3 = (k + 3 < vl) ? v.w : NINF;

    __shared__ float redm[8];
    __shared__ float reds[8];
    const int wid = tid >> 5, lid = tid & 31;

    float m = fmaxf(fmaxf(e0, e1), fmaxf(e2, e3));
    #pragma unroll
    for (int o = 16; o; o >>= 1) m = fmaxf(m, __shfl_xor_sync(~0u, m, o));
    if (lid == 0) redm[wid] = m;
    __syncthreads();
    m = redm[0];
    #pragma unroll
    for (int i = 1; i < 8; i++) m = fmaxf(m, redm[i]);

    float p0 = (k     < vl) ? __expf(e0 - m) : 0.f;
    float p1 = (k + 1 < vl) ? __expf(e1 - m) : 0.f;
    float p2 = (k + 2 < vl) ? __expf(e2 - m) : 0.f;
    float p3 = (k + 3 < vl) ? __expf(e3 - m) : 0.f;

    float s = p0 + p1 + p2 + p3;
    #pragma unroll
    for (int o = 16; o; o >>= 1) s += __shfl_xor_sync(~0u, s, o);
    if (lid == 0) reds[wid] = s;
    __syncthreads();
    s = reds[0];
    #pragma unroll
    for (int i = 1; i < 8; i++) s += reds[i];

    float inv = __frcp_rn(s);
    if (live) p[tid] = make_float4(p0 * inv, p1 * inv, p2 * inv, p3 * inv);
}

// ---------------------------------------------------------------------------
// AV partial: k split in NSLAB=4 slabs -> g_pt[s]. Tile 64q x 64v, 256 thr,
// 4q x 4v per thread (16 FFMA per 5 LDS), k-chunk 64, reg double-buffered.
// Grid (VD/64, Q/64, NSLAB*B) = (4, 8, 16) = 512 blocks.
// ---------------------------------------------------------------------------
__global__ void __launch_bounds__(256)
av_kernel(const float* __restrict__ values,
          const int* __restrict__ valid_lens) {
    __shared__ __align__(16) float at_s[64 * AT2];   // 17 KB
    __shared__ __align__(16) float vs_s[64 * 64];    // 16 KB

    const int z   = blockIdx.z;
    const int b   = z >> 2;
    const int s   = z & 3;
    const int vl  = valid_lens[b];
    const int kbeg = s * SLABK;
    if (kbeg >= vl) return;
    const int kend = (vl < kbeg + SLABK) ? vl : (kbeg + SLABK);

    const int q0  = blockIdx.y * 64;
    const int v0  = blockIdx.x * 64;
    const int tid = threadIdx.x;
    const int tx  = tid & 15;        // v cols 4tx..4tx+3
    const int ty  = tid >> 4;        // q rows 4ty..4ty+3

    const float* attn = g_sc + (size_t)(b * Qq + q0) * Kk + kbeg;
    const float* vals = values + ((size_t)b * Kk + kbeg) * VDd + v0;

    // Tile loads: 1024 f4 each, 4 per thread. e = i*256+tid: row=e>>4, c4=e&15.
    int lr[4], lc;
    lc = tid & 15;
    #pragma unroll
    for (int i = 0; i < 4; i++) lr[i] = (i * 256 + tid) >> 4;

    float4 pa[4], pv[4];
    #pragma unroll
    for (int i = 0; i < 4; i++) {
        pa[i] = ((const float4*)(attn + (size_t)lr[i] * Kk))[lc];
        pv[i] = ((const float4*)(vals + (size_t)lr[i] * VDd))[lc];
    }

    float acc[4][4];   // [qi][vj components via float4]
    float4 accv[4];
    #pragma unroll
    for (int i = 0; i < 4; i++) accv[i] = make_float4(0.f, 0.f, 0.f, 0.f);
    (void)acc;

    const int nchunk = (kend - kbeg + 63) >> 6;
    for (int c = 0; c < nchunk; c++) {
        #pragma unroll
        for (int i = 0; i < 4; i++) {
            ((float4*)(at_s + lr[i] * AT2))[lc] = pa[i];
            ((float4*)(vs_s + lr[i] * 64))[lc] = pv[i];
        }
        __syncthreads();

        if (c + 1 < nchunk) {
            const float* an = attn + (c + 1) * 64;
            const float* vn = vals + (size_t)(c + 1) * 64 * VDd;
            #pragma unroll
            for (int i = 0; i < 4; i++) {
                pa[i] = ((const float4*)(an + (size_t)lr[i] * Kk))[lc];
                pv[i] = ((const float4*)(vn + (size_t)lr[i] * VDd))[lc];
            }
        }

        const float* a0 = at_s + (4 * ty) * AT2;
        const float4* vrow = (const float4*)vs_s + tx;
        #pragma unroll 8
        for (int k = 0; k < 64; k++) {
            float w0 = a0[k];
            float w1 = a0[AT2 + k];
            float w2 = a0[2 * AT2 + k];
            float w3 = a0[3 * AT2 + k];
            float4 vv = vrow[k * 16];
            accv[0].x += w0 * vv.x; accv[0].y += w0 * vv.y;
            accv[0].z += w0 * vv.z; accv[0].w += w0 * vv.w;
            accv[1].x += w1 * vv.x; accv[1].y += w1 * vv.y;
            accv[1].z += w1 * vv.z; accv[1].w += w1 * vv.w;
            accv[2].x += w2 * vv.x; accv[2].y += w2 * vv.y;
            accv[2].z += w2 * vv.z; accv[2].w += w2 * vv.w;
            accv[3].x += w3 * vv.x; accv[3].y += w3 * vv.y;
            accv[3].z += w3 * vv.z; accv[3].w += w3 * vv.w;
        }
        __syncthreads();
    }

    float* pt = g_pt[s];
    #pragma unroll
    for (int i = 0; i < 4; i++) {
        float4* o = (float4*)(pt + (size_t)(b * Qq + q0 + 4 * ty + i) * VDd + v0);
        o[tx] = accv[i];
    }
}

// ---------------------------------------------------------------------------
// Reduce: out = sum over live slabs (s*SLABK < vl). 512 blocks x 256 thr.
// ---------------------------------------------------------------------------
__global__ void reduce_kernel(const int* __restrict__ valid_lens,
                              float* __restrict__ out) {
    const int e4 = blockIdx.x * 256 + threadIdx.x;    // float4 index
    const int b  = e4 >> 15;                          // (e4*4)/(Qq*VDd)
    const int vl = valid_lens[b];
    float4 r = ((const float4*)g_pt[0])[e4];
    #pragma unroll
    for (int s = 1; s < NSLAB; s++) {
        if (s * SLABK < vl) {
            float4 r1 = ((const float4*)g_pt[s])[e4];
            r.x += r1.x; r.y += r1.y; r.z += r1.z; r.w += r1.w;
        }
    }
    ((float4*)out)[e4] = r;
}

// ---------------------------------------------------------------------------
extern "C" void kernel_launch(void* const* d_in, const int* in_sizes, int n_in,
                              void* d_out, int out_size) {
    const float* queries    = (const float*)d_in[0];
    const float* keys       = (const float*)d_in[1];
    const float* values     = (const float*)d_in[2];
    const int*   valid_lens = (const int*)  d_in[3];
    const float* W_q        = (const float*)d_in[4];
    const float* W_k        = (const float*)d_in[5];
    const float* w_v        = (const float*)d_in[6];
    float* out = (float*)d_out;

    proj_kernel<<<(Bb * Qq) / 16 + (Bb * Kk) / 16, 256>>>(queries, W_q, keys, W_k);

    scores_kernel<<<dim3(Kk / 64, Qq / 64, Bb), 256>>>(w_v, valid_lens);

    softmax_kernel<<<Bb * Qq, 256>>>(valid_lens);

    av_kernel<<<dim3(VDd / 64, Qq / 64, NSLAB * Bb), 256>>>(values, valid_lens);

    reduce_kernel<<<(Bb * Qq * VDd) / 1024, 256>>>(valid_lens, out);
}